// round 3
// baseline (speedup 1.0000x reference)
#include <cuda_runtime.h>
#include <math.h>

// Problem constants
#define DIMC   64
#define WINN   4
#define LTOK   36     // 4 windows * 9 taps
#define WSS    128    // window spatial size

// Dynamic conv weights, layout [w][icp(32)][p(9)][oc(64)][2] (ic-pair interleaved)
__device__ float g_W[WINN * 32 * 9 * DIMC * 2];

// ---------------------------------------------------------------------------
// Stage 1: build dynamic conv kernels. One block per out-channel b. 64 blocks.
// ---------------------------------------------------------------------------
#define SQ_STRIDE 193   // 193 % 32 = 1 -> conflict-free when l varies per lane
#define SA_STRIDE 65

__global__ __launch_bounds__(288) void stage1_kernel(
    const float* __restrict__ conv_w, const float* __restrict__ w_qkv,
    const float* __restrict__ b_qkv,  const float* __restrict__ w_out,
    const float* __restrict__ b_out,  const float* __restrict__ se_w1,
    const float* __restrict__ se_b1,  const float* __restrict__ se_w2,
    const float* __restrict__ se_b2)
{
    const int b   = blockIdx.x;     // output channel 0..63
    const int tid = threadIdx.x;

    __shared__ float sA[LTOK * SA_STRIDE];   // kern0, later attn-out
    __shared__ float sQ[LTOK * SQ_STRIDE];   // qkv (stride 193), later kern2 (stride 64)
    __shared__ float pooled[4][64];
    __shared__ float hr[4][4];

    // --- load kern0: sA[l][i] = conv_w[w, b, i, p] ---
    for (int t = tid; t < LTOK * 64; t += 288) {
        int l = t >> 6, i = t & 63;
        int w = l / 9, p = l - w * 9;
        sA[l * SA_STRIDE + i] = conv_w[(((w * 64 + b) * 64 + i) * 9) + p];
    }
    __syncthreads();

    // --- qkv projection ---
    for (int t = tid; t < LTOK * 192; t += 288) {
        int l = t / 192, j = t - l * 192;
        float acc = b_qkv[j];
        const float* wr = w_qkv + j * 64;
        const float* kr = sA + l * SA_STRIDE;
        #pragma unroll
        for (int i = 0; i < 64; i++) acc = fmaf(kr[i], wr[i], acc);
        sQ[l * SQ_STRIDE + j] = acc;
    }
    __syncthreads();

    // --- attention: thread = (head h, query l) ---
    {
        int h = tid / 36, l = tid - h * 36;
        const int qo = h * 8;
        const float scale = 0.35355339059327373f;   // 8^-0.5
        float qv[8];
        #pragma unroll
        for (int d = 0; d < 8; d++) qv[d] = sQ[l * SQ_STRIDE + qo + d] * scale;

        float sc[36];
        float mx = -1e30f;
        for (int m = 0; m < 36; m++) {
            float s = 0.f;
            #pragma unroll
            for (int d = 0; d < 8; d++)
                s = fmaf(qv[d], sQ[m * SQ_STRIDE + 64 + qo + d], s);
            sc[m] = s;
            mx = fmaxf(mx, s);
        }
        float sum = 0.f;
        for (int m = 0; m < 36; m++) { float e = expf(sc[m] - mx); sc[m] = e; sum += e; }
        float inv = 1.f / sum;
        float o[8];
        #pragma unroll
        for (int d = 0; d < 8; d++) o[d] = 0.f;
        for (int m = 0; m < 36; m++) {
            float a = sc[m];
            #pragma unroll
            for (int d = 0; d < 8; d++)
                o[d] = fmaf(a, sQ[m * SQ_STRIDE + 128 + qo + d], o[d]);
        }
        #pragma unroll
        for (int d = 0; d < 8; d++) sA[l * SA_STRIDE + qo + d] = o[d] * inv;
    }
    __syncthreads();

    // --- output projection: kern2 stored in sQ with row stride 64 ---
    for (int t = tid; t < LTOK * 64; t += 288) {
        int l = t >> 6, j = t & 63;
        float acc = b_out[j];
        const float* wr = w_out + j * 64;
        const float* orow = sA + l * SA_STRIDE;
        #pragma unroll
        for (int i = 0; i < 64; i++) acc = fmaf(orow[i], wr[i], acc);
        sQ[t] = acc;
    }
    __syncthreads();

    // --- SE gating ---
    if (tid < 256) {
        int w = tid >> 6, i = tid & 63;
        float s = 0.f;
        #pragma unroll
        for (int p = 0; p < 9; p++) s += sQ[(w * 9 + p) * 64 + i];
        pooled[w][i] = s * (1.f / 9.f);
    }
    __syncthreads();
    if (tid < 16) {
        int w = tid >> 2, r = tid & 3;
        float acc = se_b1[w * 4 + r];
        #pragma unroll
        for (int i = 0; i < 64; i++)
            acc = fmaf(pooled[w][i], se_w1[(w * 4 + r) * 64 + i], acc);
        hr[w][r] = fmaxf(acc, 0.f);
    }
    __syncthreads();
    if (tid < 256) {
        int w = tid >> 6, i = tid & 63;
        float acc = se_b2[w * 64 + i];
        #pragma unroll
        for (int r = 0; r < 4; r++)
            acc = fmaf(hr[w][r], se_w2[(w * 64 + i) * 4 + r], acc);
        float g = 1.f / (1.f + expf(-acc));
        // g_W[w][i>>1][p][oc=b][i&1]
        #pragma unroll
        for (int p = 0; p < 9; p++)
            g_W[((w * 32 + (i >> 1)) * 9 + p) * 128 + b * 2 + (i & 1)] =
                sQ[(w * 9 + p) * 64 + i] * g;
    }
}

// ---------------------------------------------------------------------------
// Stage 2: dynamic 3x3 conv + channel LN + residual, packed f32x2 over ic-pairs.
// Block = 16x16 pixel tile, 64 oc, 512 threads. Thread tile: 8 oc x 4 px,
// two ic's per f32x2 lane pair. 4 K-chunks of 16 ic.
// ---------------------------------------------------------------------------
#define ICS     18                    // float stride per halo position (8 icp + 1 pad)
#define HALO_W  19                    // halo row stride in positions (18 cols + pad)
#define ISH_SZ  (342 * ICS)           // positions (y 0..17)*(19)+x(0..17) -> max 340; 342 rows
#define WSH_SZ  (8 * 9 * 128)         // 8 icp * 9 taps * 64 oc * 2
#define SMEM2_FLOATS (ISH_SZ + WSH_SZ)
#define SMEM2_BYTES  (SMEM2_FLOATS * 4)

typedef unsigned long long ull;

__device__ __forceinline__ void fma2(ull& d, ull a, ull b) {
    asm("fma.rn.f32x2 %0, %1, %2, %0;" : "+l"(d) : "l"(a), "l"(b));
}

__global__ __launch_bounds__(512, 1) void stage2_kernel(
    const float* __restrict__ x, const float* __restrict__ ln_w,
    const float* __restrict__ ln_b, float* __restrict__ out)
{
    extern __shared__ float sm[];
    float* Ish = sm;                  // [pos][ic] interleaved, stride ICS
    float* Wsh = sm + ISH_SZ;         // [icp][p][oc][2]
    // LN reduction overlays Ish after the mainloop:
    float* Rsum = sm;                 // [8][256]
    float* Rsq  = sm + 8 * 256;       // [8][256]
    float* Rmu  = sm + 16 * 256;      // [256]
    float* Rrs  = sm + 17 * 256;      // [256]

    const int blk  = blockIdx.x;
    const int tile = blk & 63;
    const int img  = blk >> 6;
    const int w    = img & 3, b = img >> 2;
    const int ty0  = (tile >> 3) << 4;
    const int tx0  = (tile & 7) << 4;
    const int wh   = w >> 1, ww = w & 1;
    const int gy0  = wh * 128 + ty0, gx0 = ww * 128 + tx0;

    const int tid = threadIdx.x;
    const int tp  = tid & 63;         // pixel group: 4 px in a row
    const int to  = tid >> 6;         // oc group 0..7
    const int oc0 = to << 3;
    const int py  = tp >> 2;          // 0..15
    const int px0 = (tp & 3) << 2;    // 0,4,8,12

    ull acc[8][4];
    #pragma unroll
    for (int o = 0; o < 8; o++)
        #pragma unroll
        for (int j = 0; j < 4; j++) acc[o][j] = 0ULL;

    const float* xb = x + (size_t)b * (64 * 256 * 256);
    const float* Wg = g_W + w * (32 * 9 * 128);

    for (int c = 0; c < 4; c++) {
        const int ic0 = c << 4;
        // ---- stage input halo chunk: Ish[(y*19+x)*ICS + ic] ----
        for (int t = tid; t < 18 * 18 * 16; t += 512) {
            int xx  = t % 18;
            int rst = t / 18;
            int yy  = rst % 18;
            int icl = rst / 18;
            int ly = ty0 + yy - 1, lx = tx0 + xx - 1;
            float v = 0.f;
            if (ly >= 0 && ly < WSS && lx >= 0 && lx < WSS)
                v = xb[(size_t)(ic0 + icl) * 65536 + (wh * 128 + ly) * 256 + (ww * 128 + lx)];
            Ish[(yy * HALO_W + xx) * ICS + icl] = v;
        }
        // ---- stage weight chunk (contiguous, pre-interleaved by stage1) ----
        {
            const float4* wsrc = (const float4*)(Wg + (c * 8) * 1152);
            float4* wdst = (float4*)Wsh;
            for (int t = tid; t < WSH_SZ / 4; t += 512) wdst[t] = wsrc[t];
        }
        __syncthreads();

        const float* Ibase0 = Ish + (py * HALO_W + px0) * ICS;
        #pragma unroll 1
        for (int icp = 0; icp < 8; icp++) {
            const float* Ib = Ibase0 + icp * 2;
            const float* Wb = Wsh + icp * 1152 + oc0 * 2;
            #pragma unroll
            for (int p = 0; p < 9; p++) {
                const int toff = ((p / 3) * HALO_W + (p % 3)) * ICS;
                ulonglong2 w01 = *(const ulonglong2*)(Wb + p * 128);
                ulonglong2 w23 = *(const ulonglong2*)(Wb + p * 128 + 4);
                ulonglong2 w45 = *(const ulonglong2*)(Wb + p * 128 + 8);
                ulonglong2 w67 = *(const ulonglong2*)(Wb + p * 128 + 12);
                ull in2[4];
                #pragma unroll
                for (int j = 0; j < 4; j++)
                    in2[j] = *(const ull*)(Ib + toff + j * ICS);
                #pragma unroll
                for (int j = 0; j < 4; j++) {
                    fma2(acc[0][j], w01.x, in2[j]);
                    fma2(acc[1][j], w01.y, in2[j]);
                    fma2(acc[2][j], w23.x, in2[j]);
                    fma2(acc[3][j], w23.y, in2[j]);
                    fma2(acc[4][j], w45.x, in2[j]);
                    fma2(acc[5][j], w45.y, in2[j]);
                    fma2(acc[6][j], w67.x, in2[j]);
                    fma2(acc[7][j], w67.y, in2[j]);
                }
            }
        }
        __syncthreads();
    }

    // ---- collapse ic-pair lanes ----
    union U { ull u; float2 f; };
    float av[8][4];
    #pragma unroll
    for (int o = 0; o < 8; o++)
        #pragma unroll
        for (int j = 0; j < 4; j++) {
            U u; u.u = acc[o][j];
            av[o][j] = u.f.x + u.f.y;
        }

    // ---- LayerNorm over channels ----
    #pragma unroll
    for (int j = 0; j < 4; j++) {
        float s = 0.f, sq = 0.f;
        #pragma unroll
        for (int o = 0; o < 8; o++) { s += av[o][j]; sq = fmaf(av[o][j], av[o][j], sq); }
        int m = py * 16 + px0 + j;
        Rsum[to * 256 + m] = s;
        Rsq [to * 256 + m] = sq;
    }
    __syncthreads();
    if (tid < 256) {
        float s = 0.f, sq = 0.f;
        #pragma unroll
        for (int g = 0; g < 8; g++) { s += Rsum[g * 256 + tid]; sq += Rsq[g * 256 + tid]; }
        float mu = s * (1.f / 64.f);
        float var = sq * (1.f / 64.f) - mu * mu;
        Rmu[tid] = mu;
        Rrs[tid] = rsqrtf(var + 1e-5f);
    }
    __syncthreads();

    float lw[8], lb[8];
    #pragma unroll
    for (int o = 0; o < 8; o++) { lw[o] = ln_w[oc0 + o]; lb[o] = ln_b[oc0 + o]; }

    #pragma unroll
    for (int j = 0; j < 4; j++) {
        int m  = py * 16 + px0 + j;
        int gy = gy0 + py;
        int gx = gx0 + px0 + j;
        float mu = Rmu[m], rs = Rrs[m];
        #pragma unroll
        for (int o = 0; o < 8; o++) {
            size_t gi = ((size_t)(b * 64 + oc0 + o) * 256 + gy) * 256 + gx;
            out[gi] = x[gi] + (av[o][j] - mu) * rs * lw[o] + lb[o];
        }
    }
}

// ---------------------------------------------------------------------------
extern "C" void kernel_launch(void* const* d_in, const int* in_sizes, int n_in,
                              void* d_out, int out_size)
{
    (void)in_sizes; (void)n_in; (void)out_size;
    const float* x      = (const float*)d_in[0];
    const float* conv_w = (const float*)d_in[1];
    const float* w_qkv  = (const float*)d_in[2];
    const float* b_qkv  = (const float*)d_in[3];
    const float* w_out  = (const float*)d_in[4];
    const float* b_out  = (const float*)d_in[5];
    const float* se_w1  = (const float*)d_in[6];
    const float* se_b1  = (const float*)d_in[7];
    const float* se_w2  = (const float*)d_in[8];
    const float* se_b2  = (const float*)d_in[9];
    const float* ln_w   = (const float*)d_in[10];
    const float* ln_b   = (const float*)d_in[11];
    float* out = (float*)d_out;

    cudaFuncSetAttribute(stage2_kernel,
                         cudaFuncAttributeMaxDynamicSharedMemorySize, SMEM2_BYTES);

    stage1_kernel<<<64, 288>>>(conv_w, w_qkv, b_qkv, w_out, b_out,
                               se_w1, se_b1, se_w2, se_b2);
    stage2_kernel<<<2048, 512, SMEM2_BYTES>>>(x, ln_w, ln_b, out);
}

// round 4
// speedup vs baseline: 1.3021x; 1.3021x over previous
#include <cuda_runtime.h>
#include <math.h>

// Problem constants
#define DIMC   64
#define WINN   4
#define LTOK   36     // 4 windows * 9 taps
#define WSS    128    // window spatial size

// Dynamic conv weights, layout [w][ic][p][oc]  (oc contiguous)
__device__ float g_W[WINN * DIMC * 9 * DIMC];

// ---------------------------------------------------------------------------
// Stage 1: build dynamic conv kernels. One block per out-channel b. 64 blocks.
// Key fix vs earlier rounds: projection loops use l = t%36 (fixed per thread),
// j = t/36 (warp-uniform) so weight LDGs are broadcast (1 wavefront) instead
// of 32 lines per load.
// ---------------------------------------------------------------------------
#define SQ_STRIDE 193   // qkv row stride (conflict-free when l varies per lane)
#define SA_STRIDE 65
#define SK_STRIDE 65    // kern2 row stride

__global__ __launch_bounds__(288) void stage1_kernel(
    const float* __restrict__ conv_w, const float* __restrict__ w_qkv,
    const float* __restrict__ b_qkv,  const float* __restrict__ w_out,
    const float* __restrict__ b_out,  const float* __restrict__ se_w1,
    const float* __restrict__ se_b1,  const float* __restrict__ se_w2,
    const float* __restrict__ se_b2)
{
    const int b   = blockIdx.x;     // output channel 0..63
    const int tid = threadIdx.x;

    __shared__ float sA[LTOK * SA_STRIDE];   // kern0, later attn-out
    __shared__ float sQ[LTOK * SQ_STRIDE];   // qkv; later kern2 (stride 65)
    __shared__ float pooled[4][64];
    __shared__ float hr[4][4];

    // --- load kern0: sA[l][i] = conv_w[w, b, i, p] ---
    for (int t = tid; t < LTOK * 64; t += 288) {
        int l = t >> 6, i = t & 63;
        int w = l / 9, p = l - w * 9;
        sA[l * SA_STRIDE + i] = conv_w[(((w * 64 + b) * 64 + i) * 9) + p];
    }
    __syncthreads();

    // --- qkv projection: l fixed per thread, j warp-uniform ---
    {
        const int l  = tid % 36;        // constant across iterations (288 = 8*36)
        const int j0 = tid / 36;
        const float* kr = sA + l * SA_STRIDE;
        for (int k = 0; k < 24; k++) {
            int j = j0 + 8 * k;
            float acc = b_qkv[j];
            const float* wr = w_qkv + j * 64;
            #pragma unroll
            for (int i = 0; i < 64; i++) acc = fmaf(kr[i], wr[i], acc);
            sQ[l * SQ_STRIDE + j] = acc;
        }
    }
    __syncthreads();

    // --- attention: thread = (head h, query l) ---
    {
        int h = tid / 36, l = tid - h * 36;
        const int qo = h * 8;
        const float scale = 0.35355339059327373f;   // 8^-0.5
        float qv[8];
        #pragma unroll
        for (int d = 0; d < 8; d++) qv[d] = sQ[l * SQ_STRIDE + qo + d] * scale;

        float sc[36];
        float mx = -1e30f;
        for (int m = 0; m < 36; m++) {
            float s = 0.f;
            #pragma unroll
            for (int d = 0; d < 8; d++)
                s = fmaf(qv[d], sQ[m * SQ_STRIDE + 64 + qo + d], s);
            sc[m] = s;
            mx = fmaxf(mx, s);
        }
        float sum = 0.f;
        for (int m = 0; m < 36; m++) { float e = expf(sc[m] - mx); sc[m] = e; sum += e; }
        float inv = 1.f / sum;
        float o[8];
        #pragma unroll
        for (int d = 0; d < 8; d++) o[d] = 0.f;
        for (int m = 0; m < 36; m++) {
            float a = sc[m];
            #pragma unroll
            for (int d = 0; d < 8; d++)
                o[d] = fmaf(a, sQ[m * SQ_STRIDE + 128 + qo + d], o[d]);
        }
        #pragma unroll
        for (int d = 0; d < 8; d++) sA[l * SA_STRIDE + qo + d] = o[d] * inv;
    }
    __syncthreads();

    // --- output projection -> kern2 in sQ (stride 65), same uniform-j trick ---
    {
        const int l  = tid % 36;
        const int j0 = tid / 36;
        const float* orow = sA + l * SA_STRIDE;
        for (int k = 0; k < 8; k++) {
            int j = j0 + 8 * k;
            float acc = b_out[j];
            const float* wr = w_out + j * 64;
            #pragma unroll
            for (int i = 0; i < 64; i++) acc = fmaf(orow[i], wr[i], acc);
            sQ[l * SK_STRIDE + j] = acc;
        }
    }
    __syncthreads();

    // --- SE gating ---
    if (tid < 256) {
        int w = tid >> 6, i = tid & 63;
        float s = 0.f;
        #pragma unroll
        for (int p = 0; p < 9; p++) s += sQ[(w * 9 + p) * SK_STRIDE + i];
        pooled[w][i] = s * (1.f / 9.f);
    }
    __syncthreads();
    if (tid < 16) {
        int w = tid >> 2, r = tid & 3;
        float acc = se_b1[w * 4 + r];
        #pragma unroll
        for (int i = 0; i < 64; i++)
            acc = fmaf(pooled[w][i], se_w1[(w * 4 + r) * 64 + i], acc);
        hr[w][r] = fmaxf(acc, 0.f);
    }
    __syncthreads();
    if (tid < 256) {
        int w = tid >> 6, i = tid & 63;
        float acc = se_b2[w * 64 + i];
        #pragma unroll
        for (int r = 0; r < 4; r++)
            acc = fmaf(hr[w][r], se_w2[(w * 64 + i) * 4 + r], acc);
        float g = 1.f / (1.f + expf(-acc));
        // g_W[w][ic=i][p][oc=b]
        #pragma unroll
        for (int p = 0; p < 9; p++)
            g_W[((w * 64 + i) * 9 + p) * 64 + b] =
                sQ[(w * 9 + p) * SK_STRIDE + i] * g;
    }
}

// ---------------------------------------------------------------------------
// Stage 2: per-window dynamic 3x3 conv + channel LN + residual.
// Block = 16x16 pixel tile, 256 threads. Thread tile: 8 oc x 8 CONSECUTIVE x.
// Per (icl,dy): load 10-value input row once, reuse across the 3 dx taps.
// ---------------------------------------------------------------------------
#define ISH_SZ   (16 * 324)          // 16 ic * 18*18
#define WSH_SZ   (16 * 9 * 64)
#define RED_SZ   (2 * 8 * 256)
#define SMEM2_BYTES ((ISH_SZ + WSH_SZ + RED_SZ) * 4)

__global__ __launch_bounds__(256, 2) void stage2_kernel(
    const float* __restrict__ x, const float* __restrict__ ln_w,
    const float* __restrict__ ln_b, float* __restrict__ out)
{
    extern __shared__ float sm[];
    float* Ish  = sm;                       // [16][18*18]
    float* Wsh  = sm + ISH_SZ;              // [16][9][64]
    float* Rsum = Wsh + WSH_SZ;             // [8][256]
    float* Rsq  = Rsum + 8 * 256;           // [8][256]

    const int blk  = blockIdx.x;
    const int tile = blk & 63;
    const int img  = blk >> 6;
    const int w    = img & 3, b = img >> 2;
    const int ty0  = (tile >> 3) << 4;
    const int tx0  = (tile & 7) << 4;
    const int wh   = w >> 1, ww = w & 1;
    const int gy0  = wh * 128 + ty0, gx0 = ww * 128 + tx0;

    const int tid  = threadIdx.x;
    const int tp   = tid & 31;      // pixel group
    const int to   = tid >> 5;      // oc group
    const int oc0  = to << 3;
    const int prow = tp >> 1;       // 0..15 tile row
    const int col0 = (tp & 1) << 3; // 0 or 8 (8 consecutive x per thread)

    float acc[8][8];                // [oc][x]
    #pragma unroll
    for (int o = 0; o < 8; o++)
        #pragma unroll
        for (int j = 0; j < 8; j++) acc[o][j] = 0.f;

    const float* xb = x + (size_t)b * (64 * 256 * 256);
    const float* Wg = g_W + w * (64 * 9 * 64);

    for (int ic0 = 0; ic0 < 64; ic0 += 16) {
        // stage input halo tile (zero pad at window boundary)
        for (int t = tid; t < ISH_SZ; t += 256) {
            int icl = t / 324;
            int rem = t - icl * 324;
            int yy = rem / 18, xx = rem - yy * 18;
            int ly = ty0 + yy - 1, lx = tx0 + xx - 1;
            float v = 0.f;
            if (ly >= 0 && ly < WSS && lx >= 0 && lx < WSS)
                v = xb[(size_t)(ic0 + icl) * 65536 + (wh * 128 + ly) * 256 + (ww * 128 + lx)];
            Ish[t] = v;
        }
        // stage weight chunk (contiguous copy)
        {
            const float* wsrc = Wg + ic0 * 576;
            for (int t = tid; t < WSH_SZ; t += 256) Wsh[t] = wsrc[t];
        }
        __syncthreads();

        #pragma unroll 1
        for (int icl = 0; icl < 16; icl++) {
            const float* Ibase = Ish + icl * 324 + prow * 18 + col0;
            const float* Wbase = Wsh + icl * 576 + oc0;
            #pragma unroll
            for (int dy = 0; dy < 3; dy++) {
                float r[10];
                #pragma unroll
                for (int i = 0; i < 10; i++) r[i] = Ibase[dy * 18 + i];
                #pragma unroll
                for (int dx = 0; dx < 3; dx++) {
                    const int p = dy * 3 + dx;
                    float4 w0 = *(const float4*)(Wbase + p * 64);
                    float4 w1 = *(const float4*)(Wbase + p * 64 + 4);
                    #pragma unroll
                    for (int j = 0; j < 8; j++) {
                        float in = r[j + dx];
                        acc[0][j] = fmaf(w0.x, in, acc[0][j]);
                        acc[1][j] = fmaf(w0.y, in, acc[1][j]);
                        acc[2][j] = fmaf(w0.z, in, acc[2][j]);
                        acc[3][j] = fmaf(w0.w, in, acc[3][j]);
                        acc[4][j] = fmaf(w1.x, in, acc[4][j]);
                        acc[5][j] = fmaf(w1.y, in, acc[5][j]);
                        acc[6][j] = fmaf(w1.z, in, acc[6][j]);
                        acc[7][j] = fmaf(w1.w, in, acc[7][j]);
                    }
                }
            }
        }
        __syncthreads();
    }

    // ---- LayerNorm over channels (deterministic staged reduction) ----
    #pragma unroll
    for (int j = 0; j < 8; j++) {
        float s = 0.f, sq = 0.f;
        #pragma unroll
        for (int o = 0; o < 8; o++) { s += acc[o][j]; sq = fmaf(acc[o][j], acc[o][j], sq); }
        int m = prow * 16 + col0 + j;
        Rsum[to * 256 + m] = s;
        Rsq [to * 256 + m] = sq;
    }
    __syncthreads();
    float mu_, rstd_;
    {
        float s = 0.f, sq = 0.f;
        #pragma unroll
        for (int g = 0; g < 8; g++) { s += Rsum[g * 256 + tid]; sq += Rsq[g * 256 + tid]; }
        mu_ = s * (1.f / 64.f);
        float var = sq * (1.f / 64.f) - mu_ * mu_;
        rstd_ = rsqrtf(var + 1e-5f);
    }
    __syncthreads();
    Rsum[tid] = mu_;
    Rsq[tid]  = rstd_;
    __syncthreads();

    float lw[8], lb[8];
    #pragma unroll
    for (int o = 0; o < 8; o++) { lw[o] = ln_w[oc0 + o]; lb[o] = ln_b[oc0 + o]; }

    const int gy = gy0 + prow;
    #pragma unroll
    for (int o = 0; o < 8; o++) {
        size_t gbase = ((size_t)(b * 64 + oc0 + o) * 256 + gy) * 256 + gx0 + col0;
        #pragma unroll
        for (int j = 0; j < 8; j++) {
            int m = prow * 16 + col0 + j;
            float mu = Rsum[m], rs = Rsq[m];
            out[gbase + j] = x[gbase + j] + (acc[o][j] - mu) * rs * lw[o] + lb[o];
        }
    }
}

// ---------------------------------------------------------------------------
extern "C" void kernel_launch(void* const* d_in, const int* in_sizes, int n_in,
                              void* d_out, int out_size)
{
    (void)in_sizes; (void)n_in; (void)out_size;
    const float* x      = (const float*)d_in[0];
    const float* conv_w = (const float*)d_in[1];
    const float* w_qkv  = (const float*)d_in[2];
    const float* b_qkv  = (const float*)d_in[3];
    const float* w_out  = (const float*)d_in[4];
    const float* b_out  = (const float*)d_in[5];
    const float* se_w1  = (const float*)d_in[6];
    const float* se_b1  = (const float*)d_in[7];
    const float* se_w2  = (const float*)d_in[8];
    const float* se_b2  = (const float*)d_in[9];
    const float* ln_w   = (const float*)d_in[10];
    const float* ln_b   = (const float*)d_in[11];
    float* out = (float*)d_out;

    cudaFuncSetAttribute(stage2_kernel,
                         cudaFuncAttributeMaxDynamicSharedMemorySize, SMEM2_BYTES);

    stage1_kernel<<<64, 288>>>(conv_w, w_qkv, b_qkv, w_out, b_out,
                               se_w1, se_b1, se_w2, se_b2);
    stage2_kernel<<<2048, 256, SMEM2_BYTES>>>(x, ln_w, ln_b, out);
}

// round 5
// speedup vs baseline: 1.4769x; 1.1342x over previous
#include <cuda_runtime.h>
#include <math.h>

// Problem constants
#define DIMC   64
#define WINN   4
#define LTOK   36     // 4 windows * 9 taps
#define WSS    128    // window spatial size

// Dynamic conv weights, layout [w][ic][p][oc]  (oc contiguous)
__device__ float g_W[WINN * DIMC * 9 * DIMC];

// ---------------------------------------------------------------------------
// Stage 1: build dynamic conv kernels. One block per out-channel b. 64 blocks.
// Projection loops: l = tid%36 fixed per thread, j warp-uniform -> broadcast
// weight LDGs.
// ---------------------------------------------------------------------------
#define SQ_STRIDE 193
#define SA_STRIDE 65
#define SK_STRIDE 65

__global__ __launch_bounds__(288) void stage1_kernel(
    const float* __restrict__ conv_w, const float* __restrict__ w_qkv,
    const float* __restrict__ b_qkv,  const float* __restrict__ w_out,
    const float* __restrict__ b_out,  const float* __restrict__ se_w1,
    const float* __restrict__ se_b1,  const float* __restrict__ se_w2,
    const float* __restrict__ se_b2)
{
    const int b   = blockIdx.x;
    const int tid = threadIdx.x;

    __shared__ float sA[LTOK * SA_STRIDE];
    __shared__ float sQ[LTOK * SQ_STRIDE];
    __shared__ float pooled[4][64];
    __shared__ float hr[4][4];

    for (int t = tid; t < LTOK * 64; t += 288) {
        int l = t >> 6, i = t & 63;
        int w = l / 9, p = l - w * 9;
        sA[l * SA_STRIDE + i] = conv_w[(((w * 64 + b) * 64 + i) * 9) + p];
    }
    __syncthreads();

    {
        const int l  = tid % 36;
        const int j0 = tid / 36;
        const float* kr = sA + l * SA_STRIDE;
        for (int k = 0; k < 24; k++) {
            int j = j0 + 8 * k;
            float acc = b_qkv[j];
            const float* wr = w_qkv + j * 64;
            #pragma unroll
            for (int i = 0; i < 64; i++) acc = fmaf(kr[i], wr[i], acc);
            sQ[l * SQ_STRIDE + j] = acc;
        }
    }
    __syncthreads();

    {
        int h = tid / 36, l = tid - h * 36;
        const int qo = h * 8;
        const float scale = 0.35355339059327373f;
        float qv[8];
        #pragma unroll
        for (int d = 0; d < 8; d++) qv[d] = sQ[l * SQ_STRIDE + qo + d] * scale;

        float sc[36];
        float mx = -1e30f;
        for (int m = 0; m < 36; m++) {
            float s = 0.f;
            #pragma unroll
            for (int d = 0; d < 8; d++)
                s = fmaf(qv[d], sQ[m * SQ_STRIDE + 64 + qo + d], s);
            sc[m] = s;
            mx = fmaxf(mx, s);
        }
        float sum = 0.f;
        for (int m = 0; m < 36; m++) { float e = expf(sc[m] - mx); sc[m] = e; sum += e; }
        float inv = 1.f / sum;
        float o[8];
        #pragma unroll
        for (int d = 0; d < 8; d++) o[d] = 0.f;
        for (int m = 0; m < 36; m++) {
            float a = sc[m];
            #pragma unroll
            for (int d = 0; d < 8; d++)
                o[d] = fmaf(a, sQ[m * SQ_STRIDE + 128 + qo + d], o[d]);
        }
        #pragma unroll
        for (int d = 0; d < 8; d++) sA[l * SA_STRIDE + qo + d] = o[d] * inv;
    }
    __syncthreads();

    {
        const int l  = tid % 36;
        const int j0 = tid / 36;
        const float* orow = sA + l * SA_STRIDE;
        for (int k = 0; k < 8; k++) {
            int j = j0 + 8 * k;
            float acc = b_out[j];
            const float* wr = w_out + j * 64;
            #pragma unroll
            for (int i = 0; i < 64; i++) acc = fmaf(orow[i], wr[i], acc);
            sQ[l * SK_STRIDE + j] = acc;
        }
    }
    __syncthreads();

    if (tid < 256) {
        int w = tid >> 6, i = tid & 63;
        float s = 0.f;
        #pragma unroll
        for (int p = 0; p < 9; p++) s += sQ[(w * 9 + p) * SK_STRIDE + i];
        pooled[w][i] = s * (1.f / 9.f);
    }
    __syncthreads();
    if (tid < 16) {
        int w = tid >> 2, r = tid & 3;
        float acc = se_b1[w * 4 + r];
        #pragma unroll
        for (int i = 0; i < 64; i++)
            acc = fmaf(pooled[w][i], se_w1[(w * 4 + r) * 64 + i], acc);
        hr[w][r] = fmaxf(acc, 0.f);
    }
    __syncthreads();
    if (tid < 256) {
        int w = tid >> 6, i = tid & 63;
        float acc = se_b2[w * 64 + i];
        #pragma unroll
        for (int r = 0; r < 4; r++)
            acc = fmaf(hr[w][r], se_w2[(w * 64 + i) * 4 + r], acc);
        float g = 1.f / (1.f + expf(-acc));
        #pragma unroll
        for (int p = 0; p < 9; p++)
            g_W[((w * 64 + i) * 9 + p) * 64 + b] =
                sQ[(w * 9 + p) * SK_STRIDE + i] * g;
    }
}

// ---------------------------------------------------------------------------
// Stage 2: dynamic 3x3 conv + channel LN + residual.
// Block = 16x16 pixel tile, 256 threads = 16 oc-groups x 16 rows.
// Thread tile: 4 oc x 16 consecutive x (one full tile row).
// Halo rows stored at stride 20 floats (16B aligned) -> inputs via 5 LDS.128
// per (icl,dy); weights via 1 broadcast LDS.128 per tap.
// ---------------------------------------------------------------------------
#define HROW    20                   // halo row stride in floats (16B aligned)
#define ISH_SZ  (16 * 18 * HROW)     // 5760 floats
#define WSH_SZ  (16 * 9 * 64)        // 9216 floats
#define SMEM2_BYTES ((ISH_SZ + WSH_SZ) * 4)

__global__ __launch_bounds__(256, 2) void stage2_kernel(
    const float* __restrict__ x, const float* __restrict__ ln_w,
    const float* __restrict__ ln_b, float* __restrict__ out)
{
    extern __shared__ float sm[];
    float* Ish = sm;                  // [16][18][20]
    float* Wsh = sm + ISH_SZ;         // [16][9][64]
    // LN reduction overlays Ish/Wsh after the mainloop:
    float* Rsum = sm;                 // [16][256]
    float* Rsq  = sm + 16 * 256;      // [16][256]
    float* Rmu  = sm + 32 * 256;      // [256]
    float* Rrs  = sm + 33 * 256;      // [256]

    const int blk  = blockIdx.x;
    const int tile = blk & 63;
    const int img  = blk >> 6;
    const int w    = img & 3, b = img >> 2;
    const int ty0  = (tile >> 3) << 4;
    const int tx0  = (tile & 7) << 4;
    const int wh   = w >> 1, ww = w & 1;
    const int gy0  = wh * 128 + ty0, gx0 = ww * 128 + tx0;

    const int tid = threadIdx.x;
    const int og  = tid >> 4;         // oc group 0..15 (4 oc each)
    const int row = tid & 15;         // tile row 0..15
    const int oc0 = og << 2;

    float acc[4][16];
    #pragma unroll
    for (int o = 0; o < 4; o++)
        #pragma unroll
        for (int j = 0; j < 16; j++) acc[o][j] = 0.f;

    const float* xb = x + (size_t)b * (64 * 256 * 256);
    const float* Wg = g_W + w * (64 * 9 * 64);

    for (int ic0 = 0; ic0 < 64; ic0 += 16) {
        // ---- stage input halo (18x18 valid region of 18x20 rows) ----
        for (int t = tid; t < 16 * 324; t += 256) {
            int icl = t / 324;
            int rem = t - icl * 324;
            int yy = rem / 18, xx = rem - yy * 18;
            int ly = ty0 + yy - 1, lx = tx0 + xx - 1;
            float v = 0.f;
            if (ly >= 0 && ly < WSS && lx >= 0 && lx < WSS)
                v = xb[(size_t)(ic0 + icl) * 65536 + (wh * 128 + ly) * 256 + (ww * 128 + lx)];
            Ish[icl * (18 * HROW) + yy * HROW + xx] = v;
        }
        // ---- stage weight chunk (contiguous float4 copy) ----
        {
            const float4* wsrc = (const float4*)(Wg + ic0 * 576);
            float4* wdst = (float4*)Wsh;
            for (int t = tid; t < WSH_SZ / 4; t += 256) wdst[t] = wsrc[t];
        }
        __syncthreads();

        #pragma unroll 1
        for (int icl = 0; icl < 16; icl++) {
            const float* Ib = Ish + icl * (18 * HROW) + row * HROW;
            const float* Wb = Wsh + icl * 576 + oc0;
            #pragma unroll
            for (int dy = 0; dy < 3; dy++) {
                float4 r4[5];
                const float4* rp = (const float4*)(Ib + dy * HROW);
                #pragma unroll
                for (int i = 0; i < 5; i++) r4[i] = rp[i];
                const float* r = (const float*)r4;
                #pragma unroll
                for (int dx = 0; dx < 3; dx++) {
                    float4 wv = *(const float4*)(Wb + (dy * 3 + dx) * 64);
                    #pragma unroll
                    for (int j = 0; j < 16; j++) {
                        float in = r[j + dx];
                        acc[0][j] = fmaf(wv.x, in, acc[0][j]);
                        acc[1][j] = fmaf(wv.y, in, acc[1][j]);
                        acc[2][j] = fmaf(wv.z, in, acc[2][j]);
                        acc[3][j] = fmaf(wv.w, in, acc[3][j]);
                    }
                }
            }
        }
        __syncthreads();
    }

    // ---- LayerNorm over channels ----
    #pragma unroll
    for (int j = 0; j < 16; j++) {
        float s = 0.f, sq = 0.f;
        #pragma unroll
        for (int o = 0; o < 4; o++) { s += acc[o][j]; sq = fmaf(acc[o][j], acc[o][j], sq); }
        int m = row * 16 + j;
        Rsum[og * 256 + m] = s;
        Rsq [og * 256 + m] = sq;
    }
    __syncthreads();
    {
        float s = 0.f, sq = 0.f;
        #pragma unroll
        for (int g = 0; g < 16; g++) { s += Rsum[g * 256 + tid]; sq += Rsq[g * 256 + tid]; }
        float mu = s * (1.f / 64.f);
        float var = sq * (1.f / 64.f) - mu * mu;
        Rmu[tid] = mu;
        Rrs[tid] = rsqrtf(var + 1e-5f);
    }
    __syncthreads();

    float lw[4], lb[4];
    #pragma unroll
    for (int o = 0; o < 4; o++) { lw[o] = ln_w[oc0 + o]; lb[o] = ln_b[oc0 + o]; }

    const int gy = gy0 + row;
    #pragma unroll
    for (int o = 0; o < 4; o++) {
        size_t gbase = ((size_t)(b * 64 + oc0 + o) * 256 + gy) * 256 + gx0;
        #pragma unroll
        for (int q = 0; q < 4; q++) {
            float4 xr = *(const float4*)(x + gbase + q * 4);
            float4 ov;
            float* ovp = (float*)&ov;
            const float* xrp = (const float*)&xr;
            #pragma unroll
            for (int e = 0; e < 4; e++) {
                int j = q * 4 + e;
                int m = row * 16 + j;
                ovp[e] = xrp[e] + (acc[o][j] - Rmu[m]) * Rrs[m] * lw[o] + lb[o];
            }
            *(float4*)(out + gbase + q * 4) = ov;
        }
    }
}

// ---------------------------------------------------------------------------
extern "C" void kernel_launch(void* const* d_in, const int* in_sizes, int n_in,
                              void* d_out, int out_size)
{
    (void)in_sizes; (void)n_in; (void)out_size;
    const float* x      = (const float*)d_in[0];
    const float* conv_w = (const float*)d_in[1];
    const float* w_qkv  = (const float*)d_in[2];
    const float* b_qkv  = (const float*)d_in[3];
    const float* w_out  = (const float*)d_in[4];
    const float* b_out  = (const float*)d_in[5];
    const float* se_w1  = (const float*)d_in[6];
    const float* se_b1  = (const float*)d_in[7];
    const float* se_w2  = (const float*)d_in[8];
    const float* se_b2  = (const float*)d_in[9];
    const float* ln_w   = (const float*)d_in[10];
    const float* ln_b   = (const float*)d_in[11];
    float* out = (float*)d_out;

    cudaFuncSetAttribute(stage2_kernel,
                         cudaFuncAttributeMaxDynamicSharedMemorySize, SMEM2_BYTES);

    stage1_kernel<<<64, 288>>>(conv_w, w_qkv, b_qkv, w_out, b_out,
                               se_w1, se_b1, se_w2, se_b2);
    stage2_kernel<<<2048, 256, SMEM2_BYTES>>>(x, ln_w, ln_b, out);
}

// round 7
// speedup vs baseline: 1.6487x; 1.1163x over previous
#include <cuda_runtime.h>
#include <cuda_bf16.h>
#include <mma.h>
#include <math.h>
#include <stdint.h>

using namespace nvcuda;

#define WINN 4
#define LTOK 36

// Dynamic conv weights, bf16 hi/lo, layout [w*9+p][ic(64)][oc stride 72]
#define WROW 72
__device__ __nv_bfloat16 g_Whi[36 * 64 * WROW];
__device__ __nv_bfloat16 g_Wlo[36 * 64 * WROW];

// ===========================================================================
// Stage 1: build dynamic conv kernels (one block per oc b = blockIdx.x).
// ===========================================================================
#define SQ_STRIDE 193
#define SA_STRIDE 65
#define SK_STRIDE 65

__global__ __launch_bounds__(288) void stage1_kernel(
    const float* __restrict__ conv_w, const float* __restrict__ w_qkv,
    const float* __restrict__ b_qkv,  const float* __restrict__ w_out,
    const float* __restrict__ b_out,  const float* __restrict__ se_w1,
    const float* __restrict__ se_b1,  const float* __restrict__ se_w2,
    const float* __restrict__ se_b2)
{
    const int b   = blockIdx.x;
    const int tid = threadIdx.x;

    __shared__ float sA[LTOK * SA_STRIDE];
    __shared__ float sQ[LTOK * SQ_STRIDE];
    __shared__ float pooled[4][64];
    __shared__ float hr[4][4];

    for (int t = tid; t < LTOK * 64; t += 288) {
        int l = t >> 6, i = t & 63;
        int w = l / 9, p = l - w * 9;
        sA[l * SA_STRIDE + i] = conv_w[(((w * 64 + b) * 64 + i) * 9) + p];
    }
    __syncthreads();

    {
        const int l  = tid % 36;
        const int j0 = tid / 36;
        const float* kr = sA + l * SA_STRIDE;
        for (int k = 0; k < 24; k++) {
            int j = j0 + 8 * k;
            float acc = b_qkv[j];
            const float* wr = w_qkv + j * 64;
            #pragma unroll
            for (int i = 0; i < 64; i++) acc = fmaf(kr[i], wr[i], acc);
            sQ[l * SQ_STRIDE + j] = acc;
        }
    }
    __syncthreads();

    {
        int h = tid / 36, l = tid - h * 36;
        const int qo = h * 8;
        const float scale = 0.35355339059327373f;
        float qv[8];
        #pragma unroll
        for (int d = 0; d < 8; d++) qv[d] = sQ[l * SQ_STRIDE + qo + d] * scale;

        float sc[36];
        float mx = -1e30f;
        for (int m = 0; m < 36; m++) {
            float s = 0.f;
            #pragma unroll
            for (int d = 0; d < 8; d++)
                s = fmaf(qv[d], sQ[m * SQ_STRIDE + 64 + qo + d], s);
            sc[m] = s;
            mx = fmaxf(mx, s);
        }
        float sum = 0.f;
        for (int m = 0; m < 36; m++) { float e = expf(sc[m] - mx); sc[m] = e; sum += e; }
        float inv = 1.f / sum;
        float o[8];
        #pragma unroll
        for (int d = 0; d < 8; d++) o[d] = 0.f;
        for (int m = 0; m < 36; m++) {
            float a = sc[m];
            #pragma unroll
            for (int d = 0; d < 8; d++)
                o[d] = fmaf(a, sQ[m * SQ_STRIDE + 128 + qo + d], o[d]);
        }
        #pragma unroll
        for (int d = 0; d < 8; d++) sA[l * SA_STRIDE + qo + d] = o[d] * inv;
    }
    __syncthreads();

    {
        const int l  = tid % 36;
        const int j0 = tid / 36;
        const float* orow = sA + l * SA_STRIDE;
        for (int k = 0; k < 8; k++) {
            int j = j0 + 8 * k;
            float acc = b_out[j];
            const float* wr = w_out + j * 64;
            #pragma unroll
            for (int i = 0; i < 64; i++) acc = fmaf(orow[i], wr[i], acc);
            sQ[l * SK_STRIDE + j] = acc;
        }
    }
    __syncthreads();

    if (tid < 256) {
        int w = tid >> 6, i = tid & 63;
        float s = 0.f;
        #pragma unroll
        for (int p = 0; p < 9; p++) s += sQ[(w * 9 + p) * SK_STRIDE + i];
        pooled[w][i] = s * (1.f / 9.f);
    }
    __syncthreads();
    if (tid < 16) {
        int w = tid >> 2, r = tid & 3;
        float acc = se_b1[w * 4 + r];
        #pragma unroll
        for (int i = 0; i < 64; i++)
            acc = fmaf(pooled[w][i], se_w1[(w * 4 + r) * 64 + i], acc);
        hr[w][r] = fmaxf(acc, 0.f);
    }
    __syncthreads();
    if (tid < 256) {
        int w = tid >> 6, i = tid & 63;   // i = ic
        float acc = se_b2[w * 64 + i];
        #pragma unroll
        for (int r = 0; r < 4; r++)
            acc = fmaf(hr[w][r], se_w2[(w * 64 + i) * 4 + r], acc);
        float g = 1.f / (1.f + expf(-acc));
        #pragma unroll
        for (int p = 0; p < 9; p++) {
            float v = sQ[(w * 9 + p) * SK_STRIDE + i] * g;
            __nv_bfloat16 hi = __float2bfloat16(v);
            __nv_bfloat16 lo = __float2bfloat16(v - __bfloat162float(hi));
            int idx = ((w * 9 + p) * 64 + i) * WROW + b;
            g_Whi[idx] = hi;
            g_Wlo[idx] = lo;
        }
    }
}

// ===========================================================================
// Stage 2: WMMA bf16-split implicit-GEMM conv + LN + residual.
// CTA = one 16x16 px tile of one (batch, window). 256 threads = 8 warps.
// Warp = 2 image rows x 64 oc. K = 2 chunks of 32 ic, 9 taps, k16 steps.
// A halo smem: [18 rows][18 cols][40]  (32 ic + 8 pad), lda = 40.
// W smem:      [9 taps][32 ic][72 oc], ldb = 72.
// ===========================================================================
#define ALDA   40
#define A_ELEMS (18 * 18 * ALDA)                 // 12960 bf16 per buffer
#define W_ELEMS (9 * 32 * WROW)                  // 20736 bf16 per buffer
#define AHI_E  0
#define ALO_E  (A_ELEMS)
#define WHI_E  (2 * A_ELEMS)
#define WLO_E  (2 * A_ELEMS + W_ELEMS)
#define SMEM2_BYTES ((2 * A_ELEMS + 2 * W_ELEMS) * 2)   // 134784 B
#define DSTRIDE 68

typedef wmma::fragment<wmma::matrix_a, 16, 16, 16, __nv_bfloat16, wmma::row_major> FragA;
typedef wmma::fragment<wmma::matrix_b, 16, 16, 16, __nv_bfloat16, wmma::row_major> FragB;
typedef wmma::fragment<wmma::accumulator, 16, 16, 16, float> FragC;

__global__ __launch_bounds__(256, 1) void stage2_kernel(
    const float* __restrict__ x, const float* __restrict__ ln_w,
    const float* __restrict__ ln_b, float* __restrict__ out)
{
    extern __shared__ __nv_bfloat16 sb[];
    __nv_bfloat16* Ahi = sb + AHI_E;
    __nv_bfloat16* Alo = sb + ALO_E;
    __nv_bfloat16* Whi = sb + WHI_E;
    __nv_bfloat16* Wlo = sb + WLO_E;

    const int blk  = blockIdx.x;
    const int tile = blk & 63;
    const int w    = (blk >> 6) & 3;
    const int b    = blk >> 8;
    const int ty0  = (tile >> 3) << 4;
    const int tx0  = (tile & 7) << 4;
    const int wh   = w >> 1, ww = w & 1;

    const int tid = threadIdx.x;
    const int wid = tid >> 5;

    FragC acc[2][4];
    #pragma unroll
    for (int r = 0; r < 2; r++)
        #pragma unroll
        for (int n = 0; n < 4; n++) wmma::fill_fragment(acc[r][n], 0.f);

    const float* xb = x + (size_t)b * (64 * 65536);

    for (int c = 0; c < 2; c++) {
        const int ic0 = c * 32;
        // ---- stage A halo: hi/lo bf16, [hrow][hcol][icl] ----
        for (int t = tid; t < 18 * 18 * 32; t += 256) {
            int hcol = t % 18;
            int rst  = t / 18;
            int hrow = rst % 18;
            int icl  = rst / 18;
            int ly = ty0 + hrow - 1, lx = tx0 + hcol - 1;
            float v = 0.f;
            if (ly >= 0 && ly < 128 && lx >= 0 && lx < 128)
                v = xb[(size_t)(ic0 + icl) * 65536 + (wh * 128 + ly) * 256 + ww * 128 + lx];
            __nv_bfloat16 hi = __float2bfloat16(v);
            __nv_bfloat16 lo = __float2bfloat16(v - __bfloat162float(hi));
            int si = (hrow * 18 + hcol) * ALDA + icl;
            Ahi[si] = hi;
            Alo[si] = lo;
        }
        // ---- stage W chunk: 9 taps x 32 ic rows x 72, uint4 copies ----
        for (int t = tid; t < 2592; t += 256) {           // 2592 = 9*288
            int tap = t / 288, rem = t - tap * 288;
            size_t so = (size_t)((w * 9 + tap) * 64 + ic0) * WROW + rem * 8;
            int   dof = tap * (32 * WROW) + rem * 8;
            *(uint4*)(Whi + dof) = *(const uint4*)(g_Whi + so);
            *(uint4*)(Wlo + dof) = *(const uint4*)(g_Wlo + so);
        }
        __syncthreads();

        // ---- mainloop ----
        #pragma unroll 1
        for (int tap = 0; tap < 9; tap++) {
            const int dy = tap / 3, dx = tap - 3 * (tap / 3);
            #pragma unroll
            for (int kc = 0; kc < 2; kc++) {
                FragB bh[4], bl[4];
                const __nv_bfloat16* wbh = Whi + (tap * 32 + kc * 16) * WROW;
                const __nv_bfloat16* wbl = Wlo + (tap * 32 + kc * 16) * WROW;
                #pragma unroll
                for (int n = 0; n < 4; n++) {
                    wmma::load_matrix_sync(bh[n], wbh + n * 16, WROW);
                    wmma::load_matrix_sync(bl[n], wbl + n * 16, WROW);
                }
                #pragma unroll
                for (int r = 0; r < 2; r++) {
                    const int yrow = wid * 2 + r;
                    const int aoff = ((yrow + dy) * 18 + dx) * ALDA + kc * 16;
                    FragA ah, al;
                    wmma::load_matrix_sync(ah, Ahi + aoff, ALDA);
                    wmma::load_matrix_sync(al, Alo + aoff, ALDA);
                    #pragma unroll
                    for (int n = 0; n < 4; n++) {
                        wmma::mma_sync(acc[r][n], ah, bh[n], acc[r][n]);
                        wmma::mma_sync(acc[r][n], al, bh[n], acc[r][n]);
                        wmma::mma_sync(acc[r][n], ah, bl[n], acc[r][n]);
                    }
                }
            }
        }
        __syncthreads();
    }

    // ---- epilogue: dump to smem, LN over oc, residual, store ----
    float* D = (float*)sb;                           // [256 px][68]
    #pragma unroll
    for (int r = 0; r < 2; r++) {
        const int yrow = wid * 2 + r;
        #pragma unroll
        for (int n = 0; n < 4; n++)
            wmma::store_matrix_sync(D + (yrow * 16) * DSTRIDE + n * 16,
                                    acc[r][n], DSTRIDE, wmma::mem_row_major);
    }
    __syncthreads();

    {
        const int y  = tid >> 4, xq = tid & 15;
        const float* drow = D + tid * DSTRIDE;
        float s = 0.f, sq = 0.f;
        #pragma unroll
        for (int oc = 0; oc < 64; oc++) {
            float d = drow[oc];
            s += d;
            sq = fmaf(d, d, sq);
        }
        float mu   = s * (1.f / 64.f);
        float rstd = rsqrtf(sq * (1.f / 64.f) - mu * mu + 1e-5f);
        const int gy = wh * 128 + ty0 + y;
        const int gx = ww * 128 + tx0 + xq;
        #pragma unroll 4
        for (int oc = 0; oc < 64; oc++) {
            size_t gi = ((size_t)(b * 64 + oc) * 256 + gy) * 256 + gx;
            out[gi] = x[gi] + (drow[oc] - mu) * rstd * ln_w[oc] + ln_b[oc];
        }
    }
}

// ===========================================================================
extern "C" void kernel_launch(void* const* d_in, const int* in_sizes, int n_in,
                              void* d_out, int out_size)
{
    (void)in_sizes; (void)n_in; (void)out_size;
    const float* x      = (const float*)d_in[0];
    const float* conv_w = (const float*)d_in[1];
    const float* w_qkv  = (const float*)d_in[2];
    const float* b_qkv  = (const float*)d_in[3];
    const float* w_out  = (const float*)d_in[4];
    const float* b_out  = (const float*)d_in[5];
    const float* se_w1  = (const float*)d_in[6];
    const float* se_b1  = (const float*)d_in[7];
    const float* se_w2  = (const float*)d_in[8];
    const float* se_b2  = (const float*)d_in[9];
    const float* ln_w   = (const float*)d_in[10];
    const float* ln_b   = (const float*)d_in[11];
    float* out = (float*)d_out;

    cudaFuncSetAttribute(stage2_kernel,
                         cudaFuncAttributeMaxDynamicSharedMemorySize, SMEM2_BYTES);

    stage1_kernel<<<64, 288>>>(conv_w, w_qkv, b_qkv, w_out, b_out,
                               se_w1, se_b1, se_w2, se_b2);
    stage2_kernel<<<2048, 256, SMEM2_BYTES>>>(x, ln_w, ln_b, out);
}

// round 9
// speedup vs baseline: 2.4192x; 1.4673x over previous
#include <cuda_runtime.h>
#include <cuda_bf16.h>
#include <mma.h>
#include <math.h>
#include <stdint.h>

using namespace nvcuda;

#define WINN 4
#define LTOK 36

// Dynamic conv weights, bf16 hi/lo, layout [w*9+p][ic(64)][oc stride 72]
#define WROW 72
__device__ __nv_bfloat16 g_Whi[36 * 64 * WROW];
__device__ __nv_bfloat16 g_Wlo[36 * 64 * WROW];

// ===========================================================================
// Stage 1: build dynamic conv kernels (one block per oc b = blockIdx.x).
// ===========================================================================
#define SQ_STRIDE 193
#define SA_STRIDE 65
#define SK_STRIDE 65

__global__ __launch_bounds__(288) void stage1_kernel(
    const float* __restrict__ conv_w, const float* __restrict__ w_qkv,
    const float* __restrict__ b_qkv,  const float* __restrict__ w_out,
    const float* __restrict__ b_out,  const float* __restrict__ se_w1,
    const float* __restrict__ se_b1,  const float* __restrict__ se_w2,
    const float* __restrict__ se_b2)
{
    const int b   = blockIdx.x;
    const int tid = threadIdx.x;

    __shared__ float sA[LTOK * SA_STRIDE];
    __shared__ float sQ[LTOK * SQ_STRIDE];
    __shared__ float pooled[4][64];
    __shared__ float hr[4][4];

    for (int t = tid; t < LTOK * 64; t += 288) {
        int l = t >> 6, i = t & 63;
        int w = l / 9, p = l - w * 9;
        sA[l * SA_STRIDE + i] = conv_w[(((w * 64 + b) * 64 + i) * 9) + p];
    }
    __syncthreads();

    {
        const int l  = tid % 36;
        const int j0 = tid / 36;
        const float* kr = sA + l * SA_STRIDE;
        for (int k = 0; k < 24; k++) {
            int j = j0 + 8 * k;
            float acc = b_qkv[j];
            const float* wr = w_qkv + j * 64;
            #pragma unroll
            for (int i = 0; i < 64; i++) acc = fmaf(kr[i], wr[i], acc);
            sQ[l * SQ_STRIDE + j] = acc;
        }
    }
    __syncthreads();

    {
        int h = tid / 36, l = tid - h * 36;
        const int qo = h * 8;
        const float scale = 0.35355339059327373f;
        float qv[8];
        #pragma unroll
        for (int d = 0; d < 8; d++) qv[d] = sQ[l * SQ_STRIDE + qo + d] * scale;

        float sc[36];
        float mx = -1e30f;
        for (int m = 0; m < 36; m++) {
            float s = 0.f;
            #pragma unroll
            for (int d = 0; d < 8; d++)
                s = fmaf(qv[d], sQ[m * SQ_STRIDE + 64 + qo + d], s);
            sc[m] = s;
            mx = fmaxf(mx, s);
        }
        float sum = 0.f;
        for (int m = 0; m < 36; m++) { float e = expf(sc[m] - mx); sc[m] = e; sum += e; }
        float inv = 1.f / sum;
        float o[8];
        #pragma unroll
        for (int d = 0; d < 8; d++) o[d] = 0.f;
        for (int m = 0; m < 36; m++) {
            float a = sc[m];
            #pragma unroll
            for (int d = 0; d < 8; d++)
                o[d] = fmaf(a, sQ[m * SQ_STRIDE + 128 + qo + d], o[d]);
        }
        #pragma unroll
        for (int d = 0; d < 8; d++) sA[l * SA_STRIDE + qo + d] = o[d] * inv;
    }
    __syncthreads();

    {
        const int l  = tid % 36;
        const int j0 = tid / 36;
        const float* orow = sA + l * SA_STRIDE;
        for (int k = 0; k < 8; k++) {
            int j = j0 + 8 * k;
            float acc = b_out[j];
            const float* wr = w_out + j * 64;
            #pragma unroll
            for (int i = 0; i < 64; i++) acc = fmaf(orow[i], wr[i], acc);
            sQ[l * SK_STRIDE + j] = acc;
        }
    }
    __syncthreads();

    if (tid < 256) {
        int w = tid >> 6, i = tid & 63;
        float s = 0.f;
        #pragma unroll
        for (int p = 0; p < 9; p++) s += sQ[(w * 9 + p) * SK_STRIDE + i];
        pooled[w][i] = s * (1.f / 9.f);
    }
    __syncthreads();
    if (tid < 16) {
        int w = tid >> 2, r = tid & 3;
        float acc = se_b1[w * 4 + r];
        #pragma unroll
        for (int i = 0; i < 64; i++)
            acc = fmaf(pooled[w][i], se_w1[(w * 4 + r) * 64 + i], acc);
        hr[w][r] = fmaxf(acc, 0.f);
    }
    __syncthreads();
    if (tid < 256) {
        int w = tid >> 6, i = tid & 63;   // i = ic
        float acc = se_b2[w * 64 + i];
        #pragma unroll
        for (int r = 0; r < 4; r++)
            acc = fmaf(hr[w][r], se_w2[(w * 64 + i) * 4 + r], acc);
        float g = 1.f / (1.f + expf(-acc));
        #pragma unroll
        for (int p = 0; p < 9; p++) {
            float v = sQ[(w * 9 + p) * SK_STRIDE + i] * g;
            __nv_bfloat16 hi = __float2bfloat16(v);
            __nv_bfloat16 lo = __float2bfloat16(v - __bfloat162float(hi));
            int idx = ((w * 9 + p) * 64 + i) * WROW + b;
            g_Whi[idx] = hi;
            g_Wlo[idx] = lo;
        }
    }
}

// ===========================================================================
// Stage 2: WMMA bf16-split implicit-GEMM conv + LN + residual.
// CTA = one 16x16 px tile. 256 threads = 8 warps, 2 CTAs/SM.
// K = 4 chunks of 16 ic, 9 taps. Warp = 2 image rows x 64 oc.
// A halo smem: [18*18 pos][24] (16 ic + 8 pad), lda = 24 elems (48B, 16B-mult)
// W smem:      [9 taps][16 ic][72 oc], ldb = 72 elems (144B, 16B-mult)
// Epilogue D:  stride 68 floats (272B = 17*16B — wmma ldm contract).
// ===========================================================================
#define ALDA   24
#define A_ELEMS (18 * 18 * ALDA)                 // 7776 bf16 per buffer
#define W_ELEMS (9 * 16 * WROW)                  // 10368 bf16 per buffer
#define AHI_E  0
#define ALO_E  (A_ELEMS)
#define WHI_E  (2 * A_ELEMS)
#define WLO_E  (2 * A_ELEMS + W_ELEMS)
#define SMEM2_BYTES ((2 * A_ELEMS + 2 * W_ELEMS) * 2)   // 72576 B
#define DSTRIDE 68

typedef wmma::fragment<wmma::matrix_a, 16, 16, 16, __nv_bfloat16, wmma::row_major> FragA;
typedef wmma::fragment<wmma::matrix_b, 16, 16, 16, __nv_bfloat16, wmma::row_major> FragB;
typedef wmma::fragment<wmma::accumulator, 16, 16, 16, float> FragC;

__global__ __launch_bounds__(256, 2) void stage2_kernel(
    const float* __restrict__ x, const float* __restrict__ ln_w,
    const float* __restrict__ ln_b, float* __restrict__ out)
{
    extern __shared__ __nv_bfloat16 sb[];
    __nv_bfloat16* Ahi = sb + AHI_E;
    __nv_bfloat16* Alo = sb + ALO_E;
    __nv_bfloat16* Whi = sb + WHI_E;
    __nv_bfloat16* Wlo = sb + WLO_E;

    const int blk  = blockIdx.x;
    const int tile = blk & 63;
    const int w    = (blk >> 6) & 3;
    const int b    = blk >> 8;
    const int ty0  = (tile >> 3) << 4;
    const int tx0  = (tile & 7) << 4;
    const int wh   = w >> 1, ww = w & 1;

    const int tid = threadIdx.x;
    const int wid = tid >> 5;

    FragC acc[2][4];
    #pragma unroll
    for (int r = 0; r < 2; r++)
        #pragma unroll
        for (int n = 0; n < 4; n++) wmma::fill_fragment(acc[r][n], 0.f);

    const float* xb = x + (size_t)b * (64 * 65536);

    #pragma unroll 1
    for (int c = 0; c < 4; c++) {
        const int ic0 = c * 16;
        // ---- stage A halo: hi/lo bf16, [pos][icl] ----
        for (int t = tid; t < 18 * 18 * 16; t += 256) {
            int hcol = t % 18;
            int rst  = t / 18;
            int hrow = rst % 18;
            int icl  = rst / 18;
            int ly = ty0 + hrow - 1, lx = tx0 + hcol - 1;
            float v = 0.f;
            if (ly >= 0 && ly < 128 && lx >= 0 && lx < 128)
                v = xb[(size_t)(ic0 + icl) * 65536 + (wh * 128 + ly) * 256 + ww * 128 + lx];
            __nv_bfloat16 hi = __float2bfloat16(v);
            __nv_bfloat16 lo = __float2bfloat16(v - __bfloat162float(hi));
            int si = (hrow * 18 + hcol) * ALDA + icl;
            Ahi[si] = hi;
            Alo[si] = lo;
        }
        // ---- stage W chunk: 9 taps x 16 ic rows x 72 oc, uint4 copies ----
        for (int t = tid; t < 1296; t += 256) {           // 1296 = 9*16*9
            int tap = t / 144, rem = t - tap * 144;       // rem: 16 rows x 9 uint4
            int row = rem / 9, q = rem - row * 9;
            size_t so = (size_t)((w * 9 + tap) * 64 + ic0 + row) * WROW + q * 8;
            int   dof = (tap * 16 + row) * WROW + q * 8;
            *(uint4*)(Whi + dof) = *(const uint4*)(g_Whi + so);
            *(uint4*)(Wlo + dof) = *(const uint4*)(g_Wlo + so);
        }
        __syncthreads();

        // ---- mainloop: 9 taps, one 16-ic k-step each ----
        #pragma unroll 1
        for (int tap = 0; tap < 9; tap++) {
            const int dy = tap / 3, dx = tap - 3 * (tap / 3);
            FragB bh[4], bl[4];
            const __nv_bfloat16* wbh = Whi + tap * 16 * WROW;
            const __nv_bfloat16* wbl = Wlo + tap * 16 * WROW;
            #pragma unroll
            for (int n = 0; n < 4; n++) {
                wmma::load_matrix_sync(bh[n], wbh + n * 16, WROW);
                wmma::load_matrix_sync(bl[n], wbl + n * 16, WROW);
            }
            #pragma unroll
            for (int r = 0; r < 2; r++) {
                const int yrow = wid * 2 + r;
                const int aoff = ((yrow + dy) * 18 + dx) * ALDA;
                FragA ah, al;
                wmma::load_matrix_sync(ah, Ahi + aoff, ALDA);
                wmma::load_matrix_sync(al, Alo + aoff, ALDA);
                #pragma unroll
                for (int n = 0; n < 4; n++) {
                    wmma::mma_sync(acc[r][n], ah, bh[n], acc[r][n]);
                    wmma::mma_sync(acc[r][n], al, bh[n], acc[r][n]);
                    wmma::mma_sync(acc[r][n], ah, bl[n], acc[r][n]);
                }
            }
        }
        __syncthreads();
    }

    // ---- epilogue: dump to smem, LN over oc, residual, store ----
    float* D = (float*)sb;                           // [256 px][68]
    #pragma unroll
    for (int r = 0; r < 2; r++) {
        const int yrow = wid * 2 + r;
        #pragma unroll
        for (int n = 0; n < 4; n++)
            wmma::store_matrix_sync(D + (yrow * 16) * DSTRIDE + n * 16,
                                    acc[r][n], DSTRIDE, wmma::mem_row_major);
    }
    __syncthreads();

    {
        const int y  = tid >> 4, xq = tid & 15;
        const float* drow = D + tid * DSTRIDE;
        float s = 0.f, sq = 0.f;
        #pragma unroll
        for (int oc = 0; oc < 64; oc++) {
            float d = drow[oc];
            s += d;
            sq = fmaf(d, d, sq);
        }
        float mu   = s * (1.f / 64.f);
        float rstd = rsqrtf(sq * (1.f / 64.f) - mu * mu + 1e-5f);
        const int gy = wh * 128 + ty0 + y;
        const int gx = ww * 128 + tx0 + xq;
        #pragma unroll 4
        for (int oc = 0; oc < 64; oc++) {
            size_t gi = ((size_t)(b * 64 + oc) * 256 + gy) * 256 + gx;
            out[gi] = x[gi] + (drow[oc] - mu) * rstd * ln_w[oc] + ln_b[oc];
        }
    }
}

// ===========================================================================
extern "C" void kernel_launch(void* const* d_in, const int* in_sizes, int n_in,
                              void* d_out, int out_size)
{
    (void)in_sizes; (void)n_in; (void)out_size;
    const float* x      = (const float*)d_in[0];
    const float* conv_w = (const float*)d_in[1];
    const float* w_qkv  = (const float*)d_in[2];
    const float* b_qkv  = (const float*)d_in[3];
    const float* w_out  = (const float*)d_in[4];
    const float* b_out  = (const float*)d_in[5];
    const float* se_w1  = (const float*)d_in[6];
    const float* se_b1  = (const float*)d_in[7];
    const float* se_w2  = (const float*)d_in[8];
    const float* se_b2  = (const float*)d_in[9];
    const float* ln_w   = (const float*)d_in[10];
    const float* ln_b   = (const float*)d_in[11];
    float* out = (float*)d_out;

    cudaFuncSetAttribute(stage2_kernel,
                         cudaFuncAttributeMaxDynamicSharedMemorySize, SMEM2_BYTES);

    stage1_kernel<<<64, 288>>>(conv_w, w_qkv, b_qkv, w_out, b_out,
                               se_w1, se_b1, se_w2, se_b2);
    stage2_kernel<<<2048, 256, SMEM2_BYTES>>>(x, ln_w, ln_b, out);
}